// round 8
// baseline (speedup 1.0000x reference)
#include <cuda_runtime.h>
#include <cuda_bf16.h>
#include <cstdint>

// ---------------------------------------------------------------------------
// Galerkin linear attention, restructured:
//   [fused] k,v = x @ w_{k,v} (tf32 mma);  in-register instance norm;
//           phase-2 emits PRE-SPLIT bf16 hi/lo in mma FRAGMENT layout;
//           phase-3 partial dots via bf16 m16n8k16 3-pass (hh+hl+lh)
//   dots = sum_chunks part ; A2 = blockdiag(dots)@w_out ; Wf[b]=w_q@A2[b]/n
//   out[b] = x[b] @ Wf[b] + b_out     (tf32 tensor-core GEMM)
// ---------------------------------------------------------------------------

#define BATCH   4
#define NTOK    8192
#define DIM     256
#define HEADS   8
#define DH      64
#define INNER   512
#define TCH     128                 // tokens per fused chunk
#define NCH     (NTOK / TCH)        // 64
#define KSEG    4                   // split-K segments for Wf

__device__ float g_part[32 * NCH * DH * DH];   // 33.5 MB partial dots
__device__ float g_dots[32 * DH * DH];
__device__ float g_A2[BATCH * INNER * DIM];
__device__ float g_WfP[KSEG * BATCH * DIM * DIM];
__device__ float g_Wf[BATCH * DIM * DIM];

__device__ __forceinline__ uint32_t f2tf32(float f) {
    uint32_t r;
    asm("cvt.rna.tf32.f32 %0, %1;" : "=r"(r) : "f"(f));
    return r;
}

__device__ __forceinline__ void mma_tf32(float* d, const uint32_t* a, const uint32_t* b) {
    asm volatile(
        "mma.sync.aligned.m16n8k8.row.col.f32.tf32.tf32.f32 "
        "{%0,%1,%2,%3}, {%4,%5,%6,%7}, {%8,%9}, {%0,%1,%2,%3};"
        : "+f"(d[0]), "+f"(d[1]), "+f"(d[2]), "+f"(d[3])
        : "r"(a[0]), "r"(a[1]), "r"(a[2]), "r"(a[3]), "r"(b[0]), "r"(b[1]));
}

__device__ __forceinline__ void mma_bf16(float* d, const uint32_t* a, const uint32_t* b) {
    asm volatile(
        "mma.sync.aligned.m16n8k16.row.col.f32.bf16.bf16.f32 "
        "{%0,%1,%2,%3}, {%4,%5,%6,%7}, {%8,%9}, {%0,%1,%2,%3};"
        : "+f"(d[0]), "+f"(d[1]), "+f"(d[2]), "+f"(d[3])
        : "r"(a[0]), "r"(a[1]), "r"(a[2]), "r"(a[3]), "r"(b[0]), "r"(b[1]));
}

// ===========================================================================
// Fused kernel. grid(NCH, 32), 256 threads, 64 KB dynamic smem.
// smem phase-1: staging As|Bk|Bv (35840 B).  After a sync, same region holds
// skh/skl/svh/svl (4 x 16 KB): bf16 hi/lo pairs in mma m16n8k16 FRAGMENT
// layout (pairs of adjacent tokens packed per 32-bit word, low = even token).
//   A-side (khat^T, m=e dh-dim, k=t token): skF[step8][mtile4][lane32][frag4]
//   B-side (vhat,  k=t, n=f dh-dim):        svF[step8][ntile8][lane32][frag2]
// ===========================================================================
#define PA 136     // As pitch (8*tg+g conflict-free)
#define PB 72      // Bk/Bv pitch
#define FUSED_SMEM 65536

__global__ __launch_bounds__(256) void fused_kv_dots(
    const float* __restrict__ x, const float* __restrict__ w_qkv,
    float* __restrict__ part)
{
    extern __shared__ unsigned char smraw[];
    uint32_t* As = (uint32_t*)smraw;           // [2][16][PA]  (x tile, tf32, [k][m])
    uint32_t* Bk = As + 2 * 16 * PA;           // [2][16][PB]
    uint32_t* Bv = Bk + 2 * 16 * PB;
    // frag arrays (alias staging; live after phase-1 sync)
    uint32_t* skh = (uint32_t*)smraw;          // 4096 words
    uint32_t* skl = skh + 4096;
    uint32_t* svh = skl + 4096;
    uint32_t* svl = svh + 4096;

    const int tid = threadIdx.x;
    const int chunk = blockIdx.x, bh = blockIdx.y;
    const int b = bh >> 3, h = bh & 7;

    const float* xA  = x + ((long long)b * NTOK + (long long)chunk * TCH) * DIM;
    const float* wkp = w_qkv + INNER + h * DH;        // stride 3*INNER
    const float* wvp = w_qkv + 2 * INNER + h * DH;

    const int xRow = tid >> 1, xC = (tid & 1) * 8;
    const int wR = tid >> 4, wC = (tid & 15) * 4;

    const int lane = tid & 31, wid = tid >> 5;
    const int g = lane >> 2, tg = lane & 3;
    const bool isV = (wid >= 4);
    const int warpM = (isV ? wid - 4 : wid) * 32;

    float acc[2][8][4];
    #pragma unroll
    for (int i = 0; i < 2; ++i)
        #pragma unroll
        for (int j = 0; j < 8; ++j)
            #pragma unroll
            for (int c = 0; c < 4; ++c) acc[i][j][c] = 0.f;

    // ---- phase 1: k/v = x @ w (K=256, 16 tiles of 16, double-buffered) ----
    float4 pa0, pa1, pk4, pv4;
    {
        pa0 = *(const float4*)&xA[(long long)xRow * DIM + xC];
        pa1 = *(const float4*)&xA[(long long)xRow * DIM + xC + 4];
        pk4 = *(const float4*)&wkp[(long long)wR * (3 * INNER) + wC];
        pv4 = *(const float4*)&wvp[(long long)wR * (3 * INNER) + wC];
    }
    As[(xC + 0) * PA + xRow] = f2tf32(pa0.x);
    As[(xC + 1) * PA + xRow] = f2tf32(pa0.y);
    As[(xC + 2) * PA + xRow] = f2tf32(pa0.z);
    As[(xC + 3) * PA + xRow] = f2tf32(pa0.w);
    As[(xC + 4) * PA + xRow] = f2tf32(pa1.x);
    As[(xC + 5) * PA + xRow] = f2tf32(pa1.y);
    As[(xC + 6) * PA + xRow] = f2tf32(pa1.z);
    As[(xC + 7) * PA + xRow] = f2tf32(pa1.w);
    {
        uint4 uk = { f2tf32(pk4.x), f2tf32(pk4.y), f2tf32(pk4.z), f2tf32(pk4.w) };
        uint4 uv = { f2tf32(pv4.x), f2tf32(pv4.y), f2tf32(pv4.z), f2tf32(pv4.w) };
        *(uint4*)&Bk[wR * PB + wC] = uk;
        *(uint4*)&Bv[wR * PB + wC] = uv;
    }
    __syncthreads();

    const uint32_t* Bsel = isV ? Bv : Bk;

    for (int kt = 0; kt < 16; ++kt) {
        const int buf = kt & 1;
        if (kt + 1 < 16) {
            const int k0 = (kt + 1) * 16;
            pa0 = *(const float4*)&xA[(long long)xRow * DIM + k0 + xC];
            pa1 = *(const float4*)&xA[(long long)xRow * DIM + k0 + xC + 4];
            pk4 = *(const float4*)&wkp[(long long)(k0 + wR) * (3 * INNER) + wC];
            pv4 = *(const float4*)&wvp[(long long)(k0 + wR) * (3 * INNER) + wC];
        }

        #pragma unroll
        for (int kk = 0; kk < 16; kk += 8) {
            uint32_t af[2][4], bf[8][2];
            #pragma unroll
            for (int mt = 0; mt < 2; ++mt) {
                const int m = warpM + mt * 16;
                af[mt][0] = As[(buf * 16 + kk + tg) * PA + m + g];
                af[mt][1] = As[(buf * 16 + kk + tg) * PA + m + g + 8];
                af[mt][2] = As[(buf * 16 + kk + tg + 4) * PA + m + g];
                af[mt][3] = As[(buf * 16 + kk + tg + 4) * PA + m + g + 8];
            }
            #pragma unroll
            for (int nt = 0; nt < 8; ++nt) {
                bf[nt][0] = Bsel[(buf * 16 + kk + tg) * PB + nt * 8 + g];
                bf[nt][1] = Bsel[(buf * 16 + kk + tg + 4) * PB + nt * 8 + g];
            }
            #pragma unroll
            for (int mt = 0; mt < 2; ++mt)
                #pragma unroll
                for (int nt = 0; nt < 8; ++nt)
                    mma_tf32(acc[mt][nt], af[mt], bf[nt]);
        }

        if (kt + 1 < 16) {
            const int nb = 1 - buf;
            As[(nb * 16 + xC + 0) * PA + xRow] = f2tf32(pa0.x);
            As[(nb * 16 + xC + 1) * PA + xRow] = f2tf32(pa0.y);
            As[(nb * 16 + xC + 2) * PA + xRow] = f2tf32(pa0.z);
            As[(nb * 16 + xC + 3) * PA + xRow] = f2tf32(pa0.w);
            As[(nb * 16 + xC + 4) * PA + xRow] = f2tf32(pa1.x);
            As[(nb * 16 + xC + 5) * PA + xRow] = f2tf32(pa1.y);
            As[(nb * 16 + xC + 6) * PA + xRow] = f2tf32(pa1.z);
            As[(nb * 16 + xC + 7) * PA + xRow] = f2tf32(pa1.w);
            uint4 uk = { f2tf32(pk4.x), f2tf32(pk4.y), f2tf32(pk4.z), f2tf32(pk4.w) };
            uint4 uv = { f2tf32(pv4.x), f2tf32(pv4.y), f2tf32(pv4.z), f2tf32(pv4.w) };
            *(uint4*)&Bk[(nb * 16 + wR) * PB + wC] = uk;
            *(uint4*)&Bv[(nb * 16 + wR) * PB + wC] = uv;
            __syncthreads();
        }
    }

    // staging is dead; frag arrays about to overwrite it.
    __syncthreads();

    // ---- phase 2: instance norm + pre-split bf16 hi/lo -> fragment layout ----
    // Thread (warpM, g, tg) owns rows r = warpM + mt*16 + g + rr*8 and
    // cols e/n = nt*8 + 2*tg + bb.  Token pairs (r, r+1) = lanes (g, g+1):
    // shfl_down(4) brings the odd token; even-g lanes pack & store.
    //   A-store (k-warps): idx = (((step)*4 + (nt>>1))*32 + (2tg+bb)*4 + (g>>1))*4
    //                            + rr*2 + (nt&1)     [step = warpM/16 + mt]
    //   B-store (v-warps): idx = (((step)*8 + nt)*32 + (2tg+bb)*4 + (g>>1))*2 + rr
    {
        const int stepb = warpM >> 4;
        #pragma unroll
        for (int mt = 0; mt < 2; ++mt) {
            #pragma unroll
            for (int rr = 0; rr < 2; ++rr) {
                float s = 0.f, q = 0.f;
                #pragma unroll
                for (int nt = 0; nt < 8; ++nt) {
                    float v0 = acc[mt][nt][2 * rr], v1 = acc[mt][nt][2 * rr + 1];
                    s += v0 + v1;
                    q += v0 * v0 + v1 * v1;
                }
                s += __shfl_xor_sync(0xFFFFFFFFu, s, 1);
                s += __shfl_xor_sync(0xFFFFFFFFu, s, 2);
                q += __shfl_xor_sync(0xFFFFFFFFu, q, 1);
                q += __shfl_xor_sync(0xFFFFFFFFu, q, 2);
                const float mu  = s * (1.0f / 64.0f);
                const float var = q * (1.0f / 64.0f) - mu * mu;
                const float inv = rsqrtf(var + 1e-5f);
                const int step = stepb + mt;
                #pragma unroll
                for (int nt = 0; nt < 8; ++nt) {
                    #pragma unroll
                    for (int bb = 0; bb < 2; ++bb) {
                        float val = (acc[mt][nt][2 * rr + bb] - mu) * inv;
                        __nv_bfloat16 hb = __float2bfloat16_rn(val);
                        float lf = val - __bfloat162float(hb);
                        __nv_bfloat16 lb = __float2bfloat16_rn(lf);
                        uint32_t own = (uint32_t)__bfloat16_as_ushort(hb)
                                     | ((uint32_t)__bfloat16_as_ushort(lb) << 16);
                        uint32_t nbr = __shfl_down_sync(0xFFFFFFFFu, own, 4);
                        if ((g & 1) == 0) {
                            uint32_t hpair, lpair;
                            asm("prmt.b32 %0, %1, %2, 0x5410;" : "=r"(hpair) : "r"(own), "r"(nbr));
                            asm("prmt.b32 %0, %1, %2, 0x7632;" : "=r"(lpair) : "r"(own), "r"(nbr));
                            const int lane2 = (2 * tg + bb) * 4 + (g >> 1);
                            if (!isV) {
                                const int widx = ((step * 4 + (nt >> 1)) * 32 + lane2) * 4
                                               + rr * 2 + (nt & 1);
                                skh[widx] = hpair;
                                skl[widx] = lpair;
                            } else {
                                const int widx = ((step * 8 + nt) * 32 + lane2) * 2 + rr;
                                svh[widx] = hpair;
                                svl[widx] = lpair;
                            }
                        }
                    }
                }
            }
        }
    }
    __syncthreads();

    // ---- phase 3: partial dots = khat^T @ vhat, bf16 3-pass (hh+hl+lh) ----
    // warp tile: m=64 (4 mtiles), n = wid*8 (1 ntile). 8 k16 steps.
    float d[4][4];
    #pragma unroll
    for (int mt = 0; mt < 4; ++mt)
        #pragma unroll
        for (int c = 0; c < 4; ++c) d[mt][c] = 0.f;

    #pragma unroll
    for (int step = 0; step < 8; ++step) {
        uint32_t ah[4][4], al[4][4], bhv[2], blv[2];
        #pragma unroll
        for (int mt = 0; mt < 4; ++mt) {
            uint4 a4 = *(const uint4*)&skh[((step * 4 + mt) * 32 + lane) * 4];
            ah[mt][0] = a4.x; ah[mt][1] = a4.y; ah[mt][2] = a4.z; ah[mt][3] = a4.w;
            uint4 l4 = *(const uint4*)&skl[((step * 4 + mt) * 32 + lane) * 4];
            al[mt][0] = l4.x; al[mt][1] = l4.y; al[mt][2] = l4.z; al[mt][3] = l4.w;
        }
        {
            uint2 b2 = *(const uint2*)&svh[((step * 8 + wid) * 32 + lane) * 2];
            bhv[0] = b2.x; bhv[1] = b2.y;
            uint2 c2 = *(const uint2*)&svl[((step * 8 + wid) * 32 + lane) * 2];
            blv[0] = c2.x; blv[1] = c2.y;
        }
        #pragma unroll
        for (int mt = 0; mt < 4; ++mt) mma_bf16(d[mt], ah[mt], bhv);
        #pragma unroll
        for (int mt = 0; mt < 4; ++mt) mma_bf16(d[mt], ah[mt], blv);
        #pragma unroll
        for (int mt = 0; mt < 4; ++mt) mma_bf16(d[mt], al[mt], bhv);
    }

    const int n0 = wid * 8;
    float* op = part + (long long)(bh * NCH + chunk) * (DH * DH);
    #pragma unroll
    for (int mt = 0; mt < 4; ++mt) {
        const int e = mt * 16 + g;
        float2 lo = { d[mt][0], d[mt][1] };
        float2 hi = { d[mt][2], d[mt][3] };
        *(float2*)&op[e * DH + n0 + 2 * tg] = lo;
        *(float2*)&op[(e + 8) * DH + n0 + 2 * tg] = hi;
    }
}

// ===========================================================================
__global__ __launch_bounds__(256) void reduce_dots(
    const float* __restrict__ part, float* __restrict__ dots)
{
    const int bh = blockIdx.x, seg = blockIdx.y;   // grid (32,4)
    #pragma unroll
    for (int j = 0; j < 4; ++j) {
        const int idx = seg * 1024 + j * 256 + threadIdx.x;
        float s = 0.f;
        #pragma unroll 8
        for (int c = 0; c < NCH; ++c)
            s += part[(long long)(bh * NCH + c) * (DH * DH) + idx];
        dots[bh * DH * DH + idx] = s;
    }
}

// A2[b, h*64+e, j] = sum_f dots[b,h][e,f] * w_out[h*64+f, j]; grid (32, 8)
__global__ __launch_bounds__(256) void dots_wout(
    const float* __restrict__ dots, const float* __restrict__ w_out,
    float* __restrict__ A2)
{
    const int bh = blockIdx.x, jt = blockIdx.y;
    const int b = bh >> 3, h = bh & 7;
    __shared__ float sd[DH * DH];
    __shared__ float sw[DH][33];
    for (int i = threadIdx.x; i < DH * DH; i += 256) sd[i] = dots[bh * DH * DH + i];
    for (int i = threadIdx.x; i < DH * 32; i += 256) {
        const int f = i >> 5, j = i & 31;
        sw[f][j] = w_out[(h * DH + f) * DIM + jt * 32 + j];
    }
    __syncthreads();
    for (int idx = threadIdx.x; idx < DH * 32; idx += 256) {
        const int e = idx >> 5, j = idx & 31;
        float s = 0.f;
        #pragma unroll 8
        for (int f = 0; f < DH; ++f) s += sd[e * DH + f] * sw[f][j];
        A2[((long long)b * INNER + h * DH + e) * DIM + jt * 32 + j] = s;
    }
}

// ===========================================================================
// WfP[seg][b] = w_q[:, seg*128:(seg+1)*128] @ A2[b][seg*128:(seg+1)*128, :]
// ===========================================================================
__global__ __launch_bounds__(256) void wf_gemm_splitk(
    const float* __restrict__ w_qkv, const float* __restrict__ A2,
    float* __restrict__ WfP)
{
    __shared__ float sA[16][68];
    __shared__ float sB[16][68];

    const int tid = threadIdx.x;
    const int m0 = blockIdx.y * 64, j0 = blockIdx.x * 64;
    const int bz = blockIdx.z;
    const int b = bz >> 2, seg = bz & 3;
    const int kbase = seg * (INNER / KSEG);

    const float* Bb = A2 + (long long)b * INNER * DIM;

    const int am = tid >> 2, akq = (tid & 3) * 4;
    const int bk = tid >> 4, bj = (tid & 15) * 4;
    const int ty = (tid >> 4) << 2;
    const int tx = (tid & 15) << 2;

    float acc[4][4] = {};

    for (int k0 = 0; k0 < INNER / KSEG; k0 += 16) {
        float4 a4 = *(const float4*)&w_qkv[(long long)(m0 + am) * (3 * INNER) + kbase + k0 + akq];
        sA[akq + 0][am] = a4.x;
        sA[akq + 1][am] = a4.y;
        sA[akq + 2][am] = a4.z;
        sA[akq + 3][am] = a4.w;
        float4 b4 = *(const float4*)&Bb[(long long)(kbase + k0 + bk) * DIM + j0 + bj];
        *(float4*)&sB[bk][bj] = b4;
        __syncthreads();
        #pragma unroll
        for (int kk = 0; kk < 16; ++kk) {
            float a[4], bb[4];
            #pragma unroll
            for (int i = 0; i < 4; ++i) a[i] = sA[kk][ty + i];
            #pragma unroll
            for (int j = 0; j < 4; ++j) bb[j] = sB[kk][tx + j];
            #pragma unroll
            for (int i = 0; i < 4; ++i)
                #pragma unroll
                for (int j = 0; j < 4; ++j) acc[i][j] += a[i] * bb[j];
        }
        __syncthreads();
    }

    float* C = WfP + ((long long)bz) * DIM * DIM;
    #pragma unroll
    for (int i = 0; i < 4; ++i) {
        float4 o = { acc[i][0], acc[i][1], acc[i][2], acc[i][3] };
        *(float4*)&C[(long long)(m0 + ty + i) * DIM + j0 + tx] = o;
    }
}

__global__ __launch_bounds__(256) void wf_reduce(
    const float* __restrict__ WfP, float* __restrict__ Wf)
{
    const int idx = blockIdx.x * 256 + threadIdx.x;
    const int b = idx / (DIM * DIM);
    const int r = idx % (DIM * DIM);
    float s = 0.f;
    #pragma unroll
    for (int seg = 0; seg < KSEG; ++seg)
        s += WfP[((long long)(b * KSEG + seg)) * DIM * DIM + r];
    Wf[idx] = s * (1.0f / (float)NTOK);
}

// ===========================================================================
// TF32 tensor-core GEMM for the final out = x @ Wf + b_out
// ===========================================================================
__global__ __launch_bounds__(256) void gemm_tf32(
    const float* __restrict__ A, int lda, long long sA,
    const float* __restrict__ B, int ldb, long long sB,
    float* __restrict__ C, int ldc, long long sC,
    int K, const float* __restrict__ bias, float alpha)
{
    __shared__ uint32_t As[2][16][132];
    __shared__ uint32_t Bs[2][16][132];

    const int tid = threadIdx.x;
    const int bx = blockIdx.x, by = blockIdx.y, bz = blockIdx.z;

    A += (long long)bz * sA + (long long)by * 128 * lda;
    B += (long long)bz * sB + (long long)bx * 128;
    C += (long long)bz * sC + (long long)by * 128 * ldc + (long long)bx * 128;

    const int aRow = tid >> 2, aCol = (tid & 3) << 2;
    const int bRow = tid >> 5, bCol = (tid & 31) << 2;

    const int lane = tid & 31, wid = tid >> 5;
    const int warpM = (wid >> 2) * 64;
    const int warpN = (wid & 3) * 32;
    const int g = lane >> 2, tg = lane & 3;

    float acc[4][4][4];
    #pragma unroll
    for (int i = 0; i < 4; ++i)
        #pragma unroll
        for (int j = 0; j < 4; ++j)
            #pragma unroll
            for (int c = 0; c < 4; ++c) acc[i][j][c] = 0.f;

    const int KT = K / 16;

    {
        float4 a0 = *reinterpret_cast<const float4*>(&A[(long long)aRow * lda + aCol]);
        float4 a1 = *reinterpret_cast<const float4*>(&A[(long long)(aRow + 64) * lda + aCol]);
        As[0][aCol + 0][aRow] = f2tf32(a0.x);
        As[0][aCol + 1][aRow] = f2tf32(a0.y);
        As[0][aCol + 2][aRow] = f2tf32(a0.z);
        As[0][aCol + 3][aRow] = f2tf32(a0.w);
        As[0][aCol + 0][aRow + 64] = f2tf32(a1.x);
        As[0][aCol + 1][aRow + 64] = f2tf32(a1.y);
        As[0][aCol + 2][aRow + 64] = f2tf32(a1.z);
        As[0][aCol + 3][aRow + 64] = f2tf32(a1.w);
        float4 b0 = *reinterpret_cast<const float4*>(&B[(long long)bRow * ldb + bCol]);
        float4 b1 = *reinterpret_cast<const float4*>(&B[(long long)(bRow + 8) * ldb + bCol]);
        uint4 u0 = { f2tf32(b0.x), f2tf32(b0.y), f2tf32(b0.z), f2tf32(b0.w) };
        uint4 u1 = { f2tf32(b1.x), f2tf32(b1.y), f2tf32(b1.z), f2tf32(b1.w) };
        *(uint4*)&Bs[0][bRow][bCol] = u0;
        *(uint4*)&Bs[0][bRow + 8][bCol] = u1;
    }
    __syncthreads();

    for (int kt = 0; kt < KT; ++kt) {
        const int buf = kt & 1;
        float4 pa0, pa1, pb0, pb1;
        if (kt + 1 < KT) {
            const int k0 = (kt + 1) * 16;
            pa0 = *reinterpret_cast<const float4*>(&A[(long long)aRow * lda + k0 + aCol]);
            pa1 = *reinterpret_cast<const float4*>(&A[(long long)(aRow + 64) * lda + k0 + aCol]);
            pb0 = *reinterpret_cast<const float4*>(&B[(long long)(k0 + bRow) * ldb + bCol]);
            pb1 = *reinterpret_cast<const float4*>(&B[(long long)(k0 + bRow + 8) * ldb + bCol]);
        }

        #pragma unroll
        for (int kk = 0; kk < 16; kk += 8) {
            uint32_t af[4][4], bf[4][2];
            #pragma unroll
            for (int mt = 0; mt < 4; ++mt) {
                const int m = warpM + mt * 16;
                af[mt][0] = As[buf][kk + tg][m + g];
                af[mt][1] = As[buf][kk + tg][m + g + 8];
                af[mt][2] = As[buf][kk + tg + 4][m + g];
                af[mt][3] = As[buf][kk + tg + 4][m + g + 8];
            }
            #pragma unroll
            for (int nt = 0; nt < 4; ++nt) {
                const int n = warpN + nt * 8;
                bf[nt][0] = Bs[buf][kk + tg][n + g];
                bf[nt][1] = Bs[buf][kk + tg + 4][n + g];
            }
            #pragma unroll
            for (int mt = 0; mt < 4; ++mt)
                #pragma unroll
                for (int nt = 0; nt < 4; ++nt)
                    mma_tf32(acc[mt][nt], af[mt], bf[nt]);
        }

        if (kt + 1 < KT) {
            const int nb = 1 - buf;
            As[nb][aCol + 0][aRow] = f2tf32(pa0.x);
            As[nb][aCol + 1][aRow] = f2tf32(pa0.y);
            As[nb][aCol + 2][aRow] = f2tf32(pa0.z);
            As[nb][aCol + 3][aRow] = f2tf32(pa0.w);
            As[nb][aCol + 0][aRow + 64] = f2tf32(pa1.x);
            As[nb][aCol + 1][aRow + 64] = f2tf32(pa1.y);
            As[nb][aCol + 2][aRow + 64] = f2tf32(pa1.z);
            As[nb][aCol + 3][aRow + 64] = f2tf32(pa1.w);
            uint4 u0 = { f2tf32(pb0.x), f2tf32(pb0.y), f2tf32(pb0.z), f2tf32(pb0.w) };
            uint4 u1 = { f2tf32(pb1.x), f2tf32(pb1.y), f2tf32(pb1.z), f2tf32(pb1.w) };
            *(uint4*)&Bs[nb][bRow][bCol] = u0;
            *(uint4*)&Bs[nb][bRow + 8][bCol] = u1;
            __syncthreads();
        }
    }

    #pragma unroll
    for (int mt = 0; mt < 4; ++mt) {
        const int r0 = warpM + mt * 16 + g;
        #pragma unroll
        for (int nt = 0; nt < 4; ++nt) {
            const int c0 = warpN + nt * 8 + 2 * tg;
            float bx0 = 0.f, bx1 = 0.f;
            if (bias) {
                const int gcol = blockIdx.x * 128 + c0;
                bx0 = bias[gcol];
                bx1 = bias[gcol + 1];
            }
            float2 lo = { alpha * acc[mt][nt][0] + bx0, alpha * acc[mt][nt][1] + bx1 };
            float2 hi = { alpha * acc[mt][nt][2] + bx0, alpha * acc[mt][nt][3] + bx1 };
            *reinterpret_cast<float2*>(&C[(long long)r0 * ldc + c0]) = lo;
            *reinterpret_cast<float2*>(&C[(long long)(r0 + 8) * ldc + c0]) = hi;
        }
    }
}

// ---------------------------------------------------------------------------
extern "C" void kernel_launch(void* const* d_in, const int* in_sizes, int n_in,
                              void* d_out, int out_size)
{
    const float* x      = (const float*)d_in[0];  // [4, 8192, 256]
    const float* w_qkv  = (const float*)d_in[1];  // [256, 1536]
    const float* w_out  = (const float*)d_in[2];  // [512, 256]
    const float* b_out  = (const float*)d_in[3];  // [256]
    float*       out    = (float*)d_out;          // [4, 8192, 256]

    float *part, *dots, *A2, *WfP, *Wf;
    cudaGetSymbolAddress((void**)&part, g_part);
    cudaGetSymbolAddress((void**)&dots, g_dots);
    cudaGetSymbolAddress((void**)&A2,   g_A2);
    cudaGetSymbolAddress((void**)&WfP,  g_WfP);
    cudaGetSymbolAddress((void**)&Wf,   g_Wf);

    cudaFuncSetAttribute(fused_kv_dots,
                         cudaFuncAttributeMaxDynamicSharedMemorySize, FUSED_SMEM);

    // 1) fused: k/v projection + instance norm + partial dots
    fused_kv_dots<<<dim3(NCH, 32), 256, FUSED_SMEM>>>(x, w_qkv, part);

    // 2) deterministic chunk reduction
    reduce_dots<<<dim3(32, 4), 256>>>(part, dots);

    // 3) A2 = blockdiag(dots) @ w_out ; Wf[b] = w_q @ A2[b] / n (split-K)
    dots_wout<<<dim3(32, 8), 256>>>(dots, w_out, A2);
    wf_gemm_splitk<<<dim3(4, 4, BATCH * KSEG), 256>>>(w_qkv, A2, WfP);
    wf_reduce<<<(BATCH * DIM * DIM) / 256, 256>>>(WfP, Wf);

    // 4) out[b] = x[b] @ Wf[b] + b_out  (tf32 TC)
    gemm_tf32<<<dim3(DIM / 128, NTOK / 128, BATCH), 256>>>(
        x, DIM, (long long)NTOK * DIM,
        Wf, DIM, (long long)DIM * DIM,
        out, DIM, (long long)NTOK * DIM,
        DIM, b_out, 1.0f);
}